// round 12
// baseline (speedup 1.0000x reference)
#include <cuda_runtime.h>

#define B_ 64
#define S_ 2048
#define I_ 128
#define H_ 512
#define O_ 128

// ---------------- scratch (device globals: no allocations allowed) ----------
__device__ float g_xin[(size_t)B_ * S_ * H_];   // input projection (B,S,H)
__device__ float g_hs [(size_t)B_ * S_ * H_];   // hidden states   (B,S,H)
__device__ float g_h[2][B_ * H_];               // double-buffered h
__device__ unsigned g_bar[16];                  // per batch-group barrier

// ---------------- helpers ----------------------------------------------------
__device__ __forceinline__ unsigned long long ffma2(unsigned long long a,
                                                    unsigned long long b,
                                                    unsigned long long c) {
    unsigned long long d;
    asm("fma.rn.f32x2 %0, %1, %2, %3;" : "=l"(d) : "l"(a), "l"(b), "l"(c));
    return d;
}
__device__ __forceinline__ unsigned long long pack2(float x, float y) {
    unsigned long long p;
    asm("mov.b64 %0, {%1, %2};" : "=l"(p) : "f"(x), "f"(y));
    return p;
}
__device__ __forceinline__ float2 unpack2(unsigned long long p) {
    float2 r;
    asm("mov.b64 {%0, %1}, %2;" : "=f"(r.x), "=f"(r.y) : "l"(p));
    return r;
}
__device__ __forceinline__ float tanh_approx(float x) {
    float r;
    asm("tanh.approx.f32 %0, %1;" : "=f"(r) : "f"(x));
    return r;
}

// ---------------- init: copy h0, reset barriers ------------------------------
__global__ void init_kernel(const float* __restrict__ h0) {
    int i = blockIdx.x * blockDim.x + threadIdx.x;
    if (i < B_ * H_) g_h[0][i] = h0[i];
    if (i < 16) g_bar[i] = 0;
}

// ---------------- dummy: shifts ncu capture alignment so scan = launch #3 ----
__global__ void dummy_kernel() {}

// ---------------- tiled fp32 GEMM:  C[M,N] = A[M,K] @ B[N,K]^T + bias --------
template <int N, int K, bool SRC_HS, bool DST_XIN>
__global__ __launch_bounds__(256) void gemm_kernel(const float* __restrict__ Ap,
                                                   const float* __restrict__ Bm,
                                                   const float* __restrict__ bias,
                                                   float* __restrict__ Cp) {
    __shared__ __align__(16) float Ast[32][132];
    __shared__ __align__(16) float Bst[32][132];
    const float* A = SRC_HS ? g_hs : Ap;
    float* C = DST_XIN ? g_xin : Cp;

    const int tid = threadIdx.x;
    const int bm = blockIdx.x, bn = blockIdx.y;
    const float* Ab = A + (size_t)bm * 128 * K;
    const float* Bb = Bm + (size_t)bn * 128 * K;

    const int tx = tid & 15, ty = tid >> 4;
    unsigned long long acc2[4][8];
#pragma unroll
    for (int i = 0; i < 4; i++)
#pragma unroll
        for (int j = 0; j < 8; j++) acc2[i][j] = 0ull;

    for (int k0 = 0; k0 < K; k0 += 32) {
#pragma unroll
        for (int u = 0; u < 4; u++) {
            int idx4 = tid + u * 256;
            int m = idx4 >> 3;
            int kq = (idx4 & 7) * 4;
            float4 va = *(const float4*)&Ab[(size_t)m * K + k0 + kq];
            Ast[kq + 0][m] = va.x; Ast[kq + 1][m] = va.y;
            Ast[kq + 2][m] = va.z; Ast[kq + 3][m] = va.w;
            float4 vb = *(const float4*)&Bb[(size_t)m * K + k0 + kq];
            Bst[kq + 0][m] = vb.x; Bst[kq + 1][m] = vb.y;
            Bst[kq + 2][m] = vb.z; Bst[kq + 3][m] = vb.w;
        }
        __syncthreads();
#pragma unroll
        for (int kc = 0; kc < 32; kc++) {
            float4 a0 = *(const float4*)&Ast[kc][ty * 8];
            float4 a1 = *(const float4*)&Ast[kc][ty * 8 + 4];
            float4 b0 = *(const float4*)&Bst[kc][tx * 8];
            float4 b1 = *(const float4*)&Bst[kc][tx * 8 + 4];
            unsigned long long A2[4] = {pack2(a0.x, a0.y), pack2(a0.z, a0.w),
                                        pack2(a1.x, a1.y), pack2(a1.z, a1.w)};
            float bb[8] = {b0.x, b0.y, b0.z, b0.w, b1.x, b1.y, b1.z, b1.w};
#pragma unroll
            for (int j = 0; j < 8; j++) {
                unsigned long long B2 = pack2(bb[j], bb[j]);
#pragma unroll
                for (int i = 0; i < 4; i++) acc2[i][j] = ffma2(A2[i], B2, acc2[i][j]);
            }
        }
        __syncthreads();
    }
#pragma unroll
    for (int i = 0; i < 4; i++) {
        size_t m0 = (size_t)bm * 128 + ty * 8 + 2 * i;
#pragma unroll
        for (int j = 0; j < 8; j++) {
            int n = bn * 128 + tx * 8 + j;
            float2 v = unpack2(acc2[i][j]);
            C[m0 * N + n]       = v.x + bias[n];
            C[(m0 + 1) * N + n] = v.y + bias[n];
        }
    }
}

// ---------------- recurrent scan ---------------------------------------------
// 128 CTAs = 16 batch-groups (4 batches) x 8 output-slices (64 cols).
// Lane (jo=lane>>3, kg=lane&7): output j = ng*64 + w*4 + jo, K-slice kg*64.
// h in smem, permuted/swizzled float4 slots (R6-proven):
//   quad kq -> slot (kq&15)*8 + ((kq>>4)^(kq&7));
//   compute read for (q,kg): slot q*8 + (kg^(q&7)) -> one 128B bcast wavefront.
// Reduce over the 8 kg lanes via shfl.bfly (replaces STS+bar+LDS+bar).
// Writers = kg<4 lanes (b=kg): 1 tanh.approx + 1 STG each (256 total, = R1).
// Exchange: L2 double buffer + R10's proven fence/atomic/poll barrier.
__global__ __launch_bounds__(512, 1) void scan_kernel(const float* __restrict__ h0,
                                                      const float* __restrict__ Wrec,
                                                      float* __restrict__ hfinal) {
    __shared__ __align__(16) float h_s[4 * H_];   // 8 KB, permuted layout

    const int tid = threadIdx.x;
    const int bg = blockIdx.x >> 3;   // 0..15
    const int ng = blockIdx.x & 7;    // 0..7
    const int w = tid >> 5, lane = tid & 31;
    const int kg = lane & 7;                       // K-slice 0..7 (64-wide)
    const int jo = lane >> 3;                      // 0..3
    const int jg = ng * 64 + w * 4 + jo;           // this lane's output col

    // ---- W_rec[jg][kg*64 .. +63] as 32 k-pair-packed f32x2 regs
    unsigned long long Wr[32];
    {
        const float4* wp = (const float4*)&Wrec[(size_t)jg * H_ + kg * 64];
#pragma unroll
        for (int q = 0; q < 16; q++) {
            float4 v = wp[q];
            Wr[2 * q]     = pack2(v.x, v.y);
            Wr[2 * q + 1] = pack2(v.z, v.w);
        }
    }

    // ---- staging identity (all 512 threads): b = tid>>7, quad kq = tid&127
    const int rb = tid >> 7;
    const int rkq = tid & 127;
    const int rslot = (rkq & 15) * 8 + (((rkq >> 4) ^ rkq) & 7);
    const size_t rsrc_off = (size_t)(bg * 4 + rb) * H_ + rkq * 4;

    const ulonglong2* h2 = (const ulonglong2*)h_s;

    // ---- writer identity: kg<4 -> (b = kg, j = jg), 256 writers total
    const bool writer = (kg < 4);
    const int bglob = bg * 4 + kg;
    float xr = 0.f;
    if (writer)
        xr = g_xin[((size_t)bglob * S_) * H_ + jg];   // xin for t=0

    const float* hsrc0 = h0;

    for (int t = 0; t < S_; t++) {
        // ---- stage h(t) into permuted smem (1 float4/thread, conflict-free)
        const float* hs_src = (t == 0) ? &hsrc0[rsrc_off]
                                       : &g_h[t & 1][rsrc_off];
        *(float4*)&h_s[(rb * 128 + rslot) * 4] = *(const float4*)hs_src;
        __syncthreads();

        // ---- partial GEMM: 16 quads x 4 batches, k-pair packed f32x2
        unsigned long long a0 = 0, a1 = 0, a2 = 0, a3 = 0;
#pragma unroll
        for (int q = 0; q < 16; q++) {
            const int sl = q * 8 + (kg ^ (q & 7));
            ulonglong2 u0 = h2[sl];
            a0 = ffma2(Wr[2 * q], u0.x, a0);
            a0 = ffma2(Wr[2 * q + 1], u0.y, a0);
            ulonglong2 u1 = h2[128 + sl];
            a1 = ffma2(Wr[2 * q], u1.x, a1);
            a1 = ffma2(Wr[2 * q + 1], u1.y, a1);
            ulonglong2 u2 = h2[256 + sl];
            a2 = ffma2(Wr[2 * q], u2.x, a2);
            a2 = ffma2(Wr[2 * q + 1], u2.y, a2);
            ulonglong2 u3 = h2[384 + sl];
            a3 = ffma2(Wr[2 * q], u3.x, a3);
            a3 = ffma2(Wr[2 * q + 1], u3.y, a3);
        }
        float2 f0 = unpack2(a0), f1 = unpack2(a1), f2 = unpack2(a2), f3 = unpack2(a3);
        float s0 = f0.x + f0.y, s1 = f1.x + f1.y, s2 = f2.x + f2.y, s3 = f3.x + f3.y;

        // ---- reduce over the 8 kg lanes (xor 1,2,4; stays within jo group)
#pragma unroll
        for (int m = 1; m < 8; m <<= 1) {
            s0 += __shfl_xor_sync(0xFFFFFFFF, s0, m);
            s1 += __shfl_xor_sync(0xFFFFFFFF, s1, m);
            s2 += __shfl_xor_sync(0xFFFFFFFF, s2, m);
            s3 += __shfl_xor_sync(0xFFFFFFFF, s3, m);
        }

        // ---- finalize on writer lanes only: 1 tanh.approx + publish h
        float hn = 0.f;
        if (writer) {
            const float sv = (kg == 0) ? s0 : (kg == 1) ? s1 : (kg == 2) ? s2 : s3;
            hn = tanh_approx(sv + xr);
            g_h[(t + 1) & 1][(size_t)bglob * H_ + jg] = hn;
            if (t == S_ - 1) hfinal[(size_t)bglob * H_ + jg] = hn;
            if (t + 1 < S_) xr = g_xin[((size_t)bglob * S_ + (t + 1)) * H_ + jg];
        }
        __syncthreads();   // all writers' h STGs issued before elected fence

        // ---- per-batch-group barrier (8 CTAs): R10's proven pattern
        if (tid == 0) {
            __threadfence();                       // publish our h slice
            atomicAdd(&g_bar[bg], 1u);
            unsigned tgt = 8u * (unsigned)(t + 1);
            while (*(volatile unsigned*)&g_bar[bg] < tgt) { }
            __threadfence();                       // acquire peers' h slices
        }

        // ---- history write: off the critical inter-CTA chain
        if (writer)
            g_hs[((size_t)bglob * S_ + t) * H_ + jg] = hn;

        __syncthreads();                           // release whole CTA
    }
}

// ---------------- launch ------------------------------------------------------
extern "C" void kernel_launch(void* const* d_in, const int* in_sizes, int n_in,
                              void* d_out, int out_size) {
    const float* inputs  = (const float*)d_in[0];
    const float* h0      = (const float*)d_in[1];
    const float* W_in_w  = (const float*)d_in[2];
    const float* W_in_b  = (const float*)d_in[3];
    const float* W_rec_w = (const float*)d_in[4];
    const float* W_out_w = (const float*)d_in[5];
    const float* W_out_b = (const float*)d_in[6];

    float* out    = (float*)d_out;                      // (B,S,O)
    float* hfinal = out + (size_t)B_ * S_ * O_;         // (B,H)

    // 1) xin = inputs @ W_in^T + b   -> g_xin          (launch #0)
    {
        dim3 grid(B_ * S_ / 128, H_ / 128);
        gemm_kernel<H_, I_, false, true><<<grid, 256>>>(inputs, W_in_w, W_in_b, nullptr);
    }
    // 2) init h double-buffer + barriers               (launch #1)
    init_kernel<<<(B_ * H_ + 255) / 256, 256>>>(h0);

    // 3) alignment dummy so ncu captures the scan      (launch #2)
    dummy_kernel<<<1, 32>>>();

    // 4) sequential scan                               (launch #3 <- ncu capture)
    scan_kernel<<<128, 512>>>(h0, W_rec_w, hfinal);

    // 5) outputs = hs @ W_out^T + b  -> d_out          (launch #4)
    {
        dim3 grid(B_ * S_ / 128, O_ / 128);
        gemm_kernel<O_, H_, true, false><<<grid, 256>>>(nullptr, W_out_w, W_out_b, out);
    }
}

// round 13
// speedup vs baseline: 1.3810x; 1.3810x over previous
#include <cuda_runtime.h>

#define B_ 64
#define S_ 2048
#define I_ 128
#define H_ 512
#define O_ 128

// ---------------- scratch (device globals: no allocations allowed) ----------
__device__ float g_xin[(size_t)B_ * S_ * H_];   // input projection (B,S,H)
__device__ float g_hs [(size_t)B_ * S_ * H_];   // hidden states   (B,S,H)
__device__ float g_h[2][B_ * H_];               // double-buffered h
// one barrier word per 128B so each batch-group hits a DIFFERENT L2 slice
// (addr->LTS hash uses bits {8,10-27}; packed words share one slice and
// serialize 128 CTAs' atomics+polls through a single LTS port)
__device__ unsigned g_bar[16][32];

// ---------------- helpers ----------------------------------------------------
__device__ __forceinline__ unsigned long long ffma2(unsigned long long a,
                                                    unsigned long long b,
                                                    unsigned long long c) {
    unsigned long long d;
    asm("fma.rn.f32x2 %0, %1, %2, %3;" : "=l"(d) : "l"(a), "l"(b), "l"(c));
    return d;
}
__device__ __forceinline__ unsigned long long pack2(float x, float y) {
    unsigned long long p;
    asm("mov.b64 %0, {%1, %2};" : "=l"(p) : "f"(x), "f"(y));
    return p;
}
__device__ __forceinline__ float2 unpack2(unsigned long long p) {
    float2 r;
    asm("mov.b64 {%0, %1}, %2;" : "=f"(r.x), "=f"(r.y) : "l"(p));
    return r;
}
__device__ __forceinline__ float tanh_approx(float x) {
    float r;
    asm("tanh.approx.f32 %0, %1;" : "=f"(r) : "f"(x));
    return r;
}

// ---------------- init: copy h0, reset barriers ------------------------------
__global__ void init_kernel(const float* __restrict__ h0) {
    int i = blockIdx.x * blockDim.x + threadIdx.x;
    if (i < B_ * H_) g_h[0][i] = h0[i];
    if (i < 16 * 32) ((unsigned*)g_bar)[i] = 0;
}

// ---------------- dummy: shifts ncu capture alignment so scan = launch #3 ----
__global__ void dummy_kernel() {}

// ---------------- tiled fp32 GEMM:  C[M,N] = A[M,K] @ B[N,K]^T + bias --------
// 128x128 block tile, 256 threads, 8x8 per-thread tile, f32x2 FMA (measured).
template <int N, int K, bool SRC_HS, bool DST_XIN>
__global__ __launch_bounds__(256) void gemm_kernel(const float* __restrict__ Ap,
                                                   const float* __restrict__ Bm,
                                                   const float* __restrict__ bias,
                                                   float* __restrict__ Cp) {
    __shared__ __align__(16) float Ast[32][132];
    __shared__ __align__(16) float Bst[32][132];
    const float* A = SRC_HS ? g_hs : Ap;
    float* C = DST_XIN ? g_xin : Cp;

    const int tid = threadIdx.x;
    const int bm = blockIdx.x, bn = blockIdx.y;
    const float* Ab = A + (size_t)bm * 128 * K;
    const float* Bb = Bm + (size_t)bn * 128 * K;

    const int tx = tid & 15, ty = tid >> 4;
    unsigned long long acc2[4][8];
#pragma unroll
    for (int i = 0; i < 4; i++)
#pragma unroll
        for (int j = 0; j < 8; j++) acc2[i][j] = 0ull;

    for (int k0 = 0; k0 < K; k0 += 32) {
#pragma unroll
        for (int u = 0; u < 4; u++) {
            int idx4 = tid + u * 256;
            int m = idx4 >> 3;
            int kq = (idx4 & 7) * 4;
            float4 va = *(const float4*)&Ab[(size_t)m * K + k0 + kq];
            Ast[kq + 0][m] = va.x; Ast[kq + 1][m] = va.y;
            Ast[kq + 2][m] = va.z; Ast[kq + 3][m] = va.w;
            float4 vb = *(const float4*)&Bb[(size_t)m * K + k0 + kq];
            Bst[kq + 0][m] = vb.x; Bst[kq + 1][m] = vb.y;
            Bst[kq + 2][m] = vb.z; Bst[kq + 3][m] = vb.w;
        }
        __syncthreads();
#pragma unroll
        for (int kc = 0; kc < 32; kc++) {
            float4 a0 = *(const float4*)&Ast[kc][ty * 8];
            float4 a1 = *(const float4*)&Ast[kc][ty * 8 + 4];
            float4 b0 = *(const float4*)&Bst[kc][tx * 8];
            float4 b1 = *(const float4*)&Bst[kc][tx * 8 + 4];
            unsigned long long A2[4] = {pack2(a0.x, a0.y), pack2(a0.z, a0.w),
                                        pack2(a1.x, a1.y), pack2(a1.z, a1.w)};
            float bb[8] = {b0.x, b0.y, b0.z, b0.w, b1.x, b1.y, b1.z, b1.w};
#pragma unroll
            for (int j = 0; j < 8; j++) {
                unsigned long long B2 = pack2(bb[j], bb[j]);
#pragma unroll
                for (int i = 0; i < 4; i++) acc2[i][j] = ffma2(A2[i], B2, acc2[i][j]);
            }
        }
        __syncthreads();
    }
#pragma unroll
    for (int i = 0; i < 4; i++) {
        size_t m0 = (size_t)bm * 128 + ty * 8 + 2 * i;
#pragma unroll
        for (int j = 0; j < 8; j++) {
            int n = bn * 128 + tx * 8 + j;
            float2 v = unpack2(acc2[i][j]);
            C[m0 * N + n]       = v.x + bias[n];
            C[(m0 + 1) * N + n] = v.y + bias[n];
        }
    }
}

// ---------------- recurrent scan (R10 proven structure, padded barrier) ------
// 128 CTAs = 16 batch-groups (4 batches) x 8 output-slices (64 cols).
// W_rec slice lives in registers (64 floats/thread as 32 f32x2 pairs).
// Per step: h (4x512) in smem -> f32x2 FMA -> partial-K reduce in smem ->
// tanh.approx -> write h slice to double-buffered global -> per-group barrier
// (now on a 128B-padded counter: one L2 slice per group) -> deferred g_hs.
__global__ __launch_bounds__(512, 1) void scan_kernel(const float* __restrict__ h0,
                                                      const float* __restrict__ Wrec,
                                                      float* __restrict__ hfinal) {
    __shared__ __align__(16) float h_s[4 * H_];   // [b][k]
    __shared__ float red[8][4][64];               // [kg][b][j]

    const int tid = threadIdx.x;
    const int bg = blockIdx.x >> 3;   // 0..15
    const int ng = blockIdx.x & 7;    // 0..7
    const int w = tid >> 5, lane = tid & 31;
    const int kg = w >> 1;                         // 0..7 -> 64-wide K slice
    const int jl = ((w & 1) << 5) | lane;          // 0..63 local output col
    const int jg = ng * 64 + jl;                   // global output col
    const int k0 = kg * 64;

    // ---- load W_rec[jg][k0..k0+63] into registers as 32 f32x2 pairs
    unsigned long long Wr[32];
    {
        const float4* wp = (const float4*)&Wrec[(size_t)jg * H_ + k0];
#pragma unroll
        for (int i = 0; i < 16; i++) {
            float4 v = wp[i];
            Wr[2 * i]     = pack2(v.x, v.y);
            Wr[2 * i + 1] = pack2(v.z, v.w);
        }
    }

    // ---- reducer identity (first 256 threads): (rb, rj)
    const int rb = tid >> 6;          // 0..3 for tid<256
    const int rj = tid & 63;
    float xr = 0.f;
    size_t xin_base = 0;
    if (tid < 256) {
        xin_base = ((size_t)(bg * 4 + rb) * S_) * H_ + (size_t)ng * 64 + rj;
        xr = g_xin[xin_base];   // xin for t=0 (gemm ran before us, stream order)
    }

    const float* hsrc0 = h0 + (size_t)bg * 4 * H_;

    for (int t = 0; t < S_; t++) {
        // ---- load h for our 4 batches into smem (2048 floats, 1 float4/thread)
        const float* hs_src = (t == 0) ? hsrc0 : &g_h[t & 1][(size_t)bg * 4 * H_];
        ((float4*)h_s)[tid] = ((const float4*)hs_src)[tid];
        __syncthreads();

        // ---- partial GEMM: acc[b] = sum over our 64-wide K slice (f32x2)
        unsigned long long acc0 = 0, acc1 = 0, acc2 = 0, acc3 = 0;
        {
            const ulonglong2* hp0 = (const ulonglong2*)&h_s[0 * H_ + k0];
            const ulonglong2* hp1 = (const ulonglong2*)&h_s[1 * H_ + k0];
            const ulonglong2* hp2 = (const ulonglong2*)&h_s[2 * H_ + k0];
            const ulonglong2* hp3 = (const ulonglong2*)&h_s[3 * H_ + k0];
#pragma unroll
            for (int i = 0; i < 16; i++) {
                ulonglong2 u0 = hp0[i];
                acc0 = ffma2(Wr[2 * i], u0.x, acc0);
                acc0 = ffma2(Wr[2 * i + 1], u0.y, acc0);
                ulonglong2 u1 = hp1[i];
                acc1 = ffma2(Wr[2 * i], u1.x, acc1);
                acc1 = ffma2(Wr[2 * i + 1], u1.y, acc1);
                ulonglong2 u2 = hp2[i];
                acc2 = ffma2(Wr[2 * i], u2.x, acc2);
                acc2 = ffma2(Wr[2 * i + 1], u2.y, acc2);
                ulonglong2 u3 = hp3[i];
                acc3 = ffma2(Wr[2 * i], u3.x, acc3);
                acc3 = ffma2(Wr[2 * i + 1], u3.y, acc3);
            }
        }
        float2 a0 = unpack2(acc0), a1 = unpack2(acc1);
        float2 a2 = unpack2(acc2), a3 = unpack2(acc3);
        red[kg][0][jl] = a0.x + a0.y;
        red[kg][1][jl] = a1.x + a1.y;
        red[kg][2][jl] = a2.x + a2.y;
        red[kg][3][jl] = a3.x + a3.y;
        __syncthreads();

        // ---- reduce over 8 K-slices, add xin, tanh.approx, publish h
        float hn = 0.f;
        int bglob = 0;
        if (tid < 256) {
            float s = xr;
#pragma unroll
            for (int q = 0; q < 8; q++) s += red[q][rb][rj];
            hn = tanh_approx(s);
            bglob = bg * 4 + rb;
            g_h[(t + 1) & 1][(size_t)bglob * H_ + ng * 64 + rj] = hn;
            if (t == S_ - 1) hfinal[(size_t)bglob * H_ + ng * 64 + rj] = hn;
            if (t + 1 < S_) xr = g_xin[xin_base + (size_t)(t + 1) * H_]; // prefetch
        }
        __syncthreads();   // all h writes issued before the elected fence

        // ---- per-batch-group barrier (8 CTAs), slice-padded counter
        if (tid == 0) {
            __threadfence();                       // publish our h slice gpu-wide
            atomicAdd(&g_bar[bg][0], 1u);
            unsigned tgt = 8u * (unsigned)(t + 1);
            while (*(volatile unsigned*)&g_bar[bg][0] < tgt) { }
            __threadfence();                       // acquire peers' h slices
        }

        // ---- history write: off the critical inter-CTA chain
        if (tid < 256)
            g_hs[((size_t)bglob * S_ + t) * H_ + ng * 64 + rj] = hn;

        __syncthreads();                           // release whole CTA
    }
}

// ---------------- launch ------------------------------------------------------
extern "C" void kernel_launch(void* const* d_in, const int* in_sizes, int n_in,
                              void* d_out, int out_size) {
    const float* inputs  = (const float*)d_in[0];
    const float* h0      = (const float*)d_in[1];
    const float* W_in_w  = (const float*)d_in[2];
    const float* W_in_b  = (const float*)d_in[3];
    const float* W_rec_w = (const float*)d_in[4];
    const float* W_out_w = (const float*)d_in[5];
    const float* W_out_b = (const float*)d_in[6];

    float* out    = (float*)d_out;                      // (B,S,O)
    float* hfinal = out + (size_t)B_ * S_ * O_;         // (B,H)

    // 1) xin = inputs @ W_in^T + b   -> g_xin          (launch #0)
    {
        dim3 grid(B_ * S_ / 128, H_ / 128);
        gemm_kernel<H_, I_, false, true><<<grid, 256>>>(inputs, W_in_w, W_in_b, nullptr);
    }
    // 2) init h double-buffer + barriers               (launch #1)
    init_kernel<<<(B_ * H_ + 255) / 256, 256>>>(h0);

    // 3) alignment dummy so ncu captures the scan      (launch #2)
    dummy_kernel<<<1, 32>>>();

    // 4) sequential scan                               (launch #3 <- ncu capture)
    scan_kernel<<<128, 512>>>(h0, W_rec_w, hfinal);

    // 5) outputs = hs @ W_out^T + b  -> d_out          (launch #4)
    {
        dim3 grid(B_ * S_ / 128, O_ / 128);
        gemm_kernel<O_, H_, true, false><<<grid, 256>>>(nullptr, W_out_w, W_out_b, out);
    }
}

// round 15
// speedup vs baseline: 1.4260x; 1.0325x over previous
#include <cuda_runtime.h>

#define B_ 64
#define S_ 2048
#define I_ 128
#define H_ 512
#define O_ 128

// ---------------- scratch (device globals: no allocations allowed) ----------
__device__ float g_xin[(size_t)B_ * S_ * H_];   // input projection (B,S,H)
__device__ float g_hs [(size_t)B_ * S_ * H_];   // hidden states   (B,S,H)
__device__ float g_h[2][B_ * H_];               // double-buffered h
__device__ unsigned g_bar[16][32];              // 128B-padded per-group barrier

// ---------------- helpers ----------------------------------------------------
__device__ __forceinline__ unsigned long long ffma2(unsigned long long a,
                                                    unsigned long long b,
                                                    unsigned long long c) {
    unsigned long long d;
    asm("fma.rn.f32x2 %0, %1, %2, %3;" : "=l"(d) : "l"(a), "l"(b), "l"(c));
    return d;
}
__device__ __forceinline__ unsigned long long pack2(float x, float y) {
    unsigned long long p;
    asm("mov.b64 %0, {%1, %2};" : "=l"(p) : "f"(x), "f"(y));
    return p;
}
__device__ __forceinline__ float2 unpack2(unsigned long long p) {
    float2 r;
    asm("mov.b64 {%0, %1}, %2;" : "=f"(r.x), "=f"(r.y) : "l"(p));
    return r;
}
__device__ __forceinline__ float tanh_approx(float x) {
    float r;
    asm("tanh.approx.f32 %0, %1;" : "=f"(r) : "f"(x));
    return r;
}

// ---------------- init: copy h0, reset barriers ------------------------------
__global__ void init_kernel(const float* __restrict__ h0) {
    int i = blockIdx.x * blockDim.x + threadIdx.x;
    if (i < B_ * H_) g_h[0][i] = h0[i];
    if (i < 16 * 32) ((unsigned*)g_bar)[i] = 0;
}

// ---------------- dummy: shifts ncu capture alignment so scan = launch #3 ----
__global__ void dummy_kernel() {}

// ---------------- tiled fp32 GEMM:  C[M,N] = A[M,K] @ B[N,K]^T + bias --------
// 128x128 block tile, 256 threads, 8x8 per-thread tile, f32x2 FMA.
// B register tile split: thread covers n = tx*4..+3 and 64+tx*4..+3, so each
// 8-lane LDS.128 phase reads 16B slots mb=tx (all 32 banks) -> conflict-free
// B compute reads (was 2-way: mb=2*tx hit only even slots). Stride 132 (16B
// aligned). A-reads are broadcast (ty-only address).
template <int N, int K, bool SRC_HS, bool DST_XIN>
__global__ __launch_bounds__(256) void gemm_kernel(const float* __restrict__ Ap,
                                                   const float* __restrict__ Bm,
                                                   const float* __restrict__ bias,
                                                   float* __restrict__ Cp) {
    __shared__ __align__(16) float Ast[32][132];
    __shared__ __align__(16) float Bst[32][132];
    const float* A = SRC_HS ? g_hs : Ap;
    float* C = DST_XIN ? g_xin : Cp;

    const int tid = threadIdx.x;
    const int bm = blockIdx.x, bn = blockIdx.y;
    const float* Ab = A + (size_t)bm * 128 * K;
    const float* Bb = Bm + (size_t)bn * 128 * K;

    const int tx = tid & 15, ty = tid >> 4;
    unsigned long long acc2[4][8];
#pragma unroll
    for (int i = 0; i < 4; i++)
#pragma unroll
        for (int j = 0; j < 8; j++) acc2[i][j] = 0ull;

    for (int k0 = 0; k0 < K; k0 += 32) {
#pragma unroll
        for (int u = 0; u < 4; u++) {
            int idx4 = tid + u * 256;
            int m = idx4 >> 3;
            int kq = (idx4 & 7) * 4;
            float4 va = *(const float4*)&Ab[(size_t)m * K + k0 + kq];
            Ast[kq + 0][m] = va.x; Ast[kq + 1][m] = va.y;
            Ast[kq + 2][m] = va.z; Ast[kq + 3][m] = va.w;
            float4 vb = *(const float4*)&Bb[(size_t)m * K + k0 + kq];
            Bst[kq + 0][m] = vb.x; Bst[kq + 1][m] = vb.y;
            Bst[kq + 2][m] = vb.z; Bst[kq + 3][m] = vb.w;
        }
        __syncthreads();
#pragma unroll
        for (int kc = 0; kc < 32; kc++) {
            float4 a0 = *(const float4*)&Ast[kc][ty * 8];
            float4 a1 = *(const float4*)&Ast[kc][ty * 8 + 4];
            float4 b0 = *(const float4*)&Bst[kc][tx * 4];        // mb = tx
            float4 b1 = *(const float4*)&Bst[kc][64 + tx * 4];   // mb = 16+tx
            unsigned long long A2[4] = {pack2(a0.x, a0.y), pack2(a0.z, a0.w),
                                        pack2(a1.x, a1.y), pack2(a1.z, a1.w)};
            float bb[8] = {b0.x, b0.y, b0.z, b0.w, b1.x, b1.y, b1.z, b1.w};
#pragma unroll
            for (int j = 0; j < 8; j++) {
                unsigned long long B2 = pack2(bb[j], bb[j]);
#pragma unroll
                for (int i = 0; i < 4; i++) acc2[i][j] = ffma2(A2[i], B2, acc2[i][j]);
            }
        }
        __syncthreads();
    }
#pragma unroll
    for (int i = 0; i < 4; i++) {
        size_t m0 = (size_t)bm * 128 + ty * 8 + 2 * i;
#pragma unroll
        for (int j = 0; j < 8; j++) {
            int n = bn * 128 + (j < 4 ? tx * 4 + j : 64 + tx * 4 + (j - 4));
            float2 v = unpack2(acc2[i][j]);
            C[m0 * N + n]       = v.x + bias[n];
            C[(m0 + 1) * N + n] = v.y + bias[n];
        }
    }
}

// ---------------- recurrent scan (R13 frozen — best measured) ----------------
__global__ __launch_bounds__(512, 1) void scan_kernel(const float* __restrict__ h0,
                                                      const float* __restrict__ Wrec,
                                                      float* __restrict__ hfinal) {
    __shared__ __align__(16) float h_s[4 * H_];   // [b][k]
    __shared__ float red[8][4][64];               // [kg][b][j]

    const int tid = threadIdx.x;
    const int bg = blockIdx.x >> 3;   // 0..15
    const int ng = blockIdx.x & 7;    // 0..7
    const int w = tid >> 5, lane = tid & 31;
    const int kg = w >> 1;                         // 0..7 -> 64-wide K slice
    const int jl = ((w & 1) << 5) | lane;          // 0..63 local output col
    const int jg = ng * 64 + jl;                   // global output col
    const int k0 = kg * 64;

    // ---- load W_rec[jg][k0..k0+63] into registers as 32 f32x2 pairs
    unsigned long long Wr[32];
    {
        const float4* wp = (const float4*)&Wrec[(size_t)jg * H_ + k0];
#pragma unroll
        for (int i = 0; i < 16; i++) {
            float4 v = wp[i];
            Wr[2 * i]     = pack2(v.x, v.y);
            Wr[2 * i + 1] = pack2(v.z, v.w);
        }
    }

    // ---- reducer identity (first 256 threads): (rb, rj)
    const int rb = tid >> 6;          // 0..3 for tid<256
    const int rj = tid & 63;
    float xr = 0.f;
    size_t xin_base = 0;
    if (tid < 256) {
        xin_base = ((size_t)(bg * 4 + rb) * S_) * H_ + (size_t)ng * 64 + rj;
        xr = g_xin[xin_base];   // xin for t=0 (gemm ran before us, stream order)
    }

    const float* hsrc0 = h0 + (size_t)bg * 4 * H_;

    for (int t = 0; t < S_; t++) {
        // ---- load h for our 4 batches into smem (2048 floats, 1 float4/thread)
        const float* hs_src = (t == 0) ? hsrc0 : &g_h[t & 1][(size_t)bg * 4 * H_];
        ((float4*)h_s)[tid] = ((const float4*)hs_src)[tid];
        __syncthreads();

        // ---- partial GEMM: acc[b] = sum over our 64-wide K slice (f32x2)
        unsigned long long acc0 = 0, acc1 = 0, acc2 = 0, acc3 = 0;
        {
            const ulonglong2* hp0 = (const ulonglong2*)&h_s[0 * H_ + k0];
            const ulonglong2* hp1 = (const ulonglong2*)&h_s[1 * H_ + k0];
            const ulonglong2* hp2 = (const ulonglong2*)&h_s[2 * H_ + k0];
            const ulonglong2* hp3 = (const ulonglong2*)&h_s[3 * H_ + k0];
#pragma unroll
            for (int i = 0; i < 16; i++) {
                ulonglong2 u0 = hp0[i];
                acc0 = ffma2(Wr[2 * i], u0.x, acc0);
                acc0 = ffma2(Wr[2 * i + 1], u0.y, acc0);
                ulonglong2 u1 = hp1[i];
                acc1 = ffma2(Wr[2 * i], u1.x, acc1);
                acc1 = ffma2(Wr[2 * i + 1], u1.y, acc1);
                ulonglong2 u2 = hp2[i];
                acc2 = ffma2(Wr[2 * i], u2.x, acc2);
                acc2 = ffma2(Wr[2 * i + 1], u2.y, acc2);
                ulonglong2 u3 = hp3[i];
                acc3 = ffma2(Wr[2 * i], u3.x, acc3);
                acc3 = ffma2(Wr[2 * i + 1], u3.y, acc3);
            }
        }
        float2 a0 = unpack2(acc0), a1 = unpack2(acc1);
        float2 a2 = unpack2(acc2), a3 = unpack2(acc3);
        red[kg][0][jl] = a0.x + a0.y;
        red[kg][1][jl] = a1.x + a1.y;
        red[kg][2][jl] = a2.x + a2.y;
        red[kg][3][jl] = a3.x + a3.y;
        __syncthreads();

        // ---- reduce over 8 K-slices, add xin, tanh.approx, publish h
        float hn = 0.f;
        int bglob = 0;
        if (tid < 256) {
            float s = xr;
#pragma unroll
            for (int q = 0; q < 8; q++) s += red[q][rb][rj];
            hn = tanh_approx(s);
            bglob = bg * 4 + rb;
            g_h[(t + 1) & 1][(size_t)bglob * H_ + ng * 64 + rj] = hn;
            if (t == S_ - 1) hfinal[(size_t)bglob * H_ + ng * 64 + rj] = hn;
            if (t + 1 < S_) xr = g_xin[xin_base + (size_t)(t + 1) * H_]; // prefetch
        }
        __syncthreads();   // all h writes issued before the elected fence

        // ---- per-batch-group barrier (8 CTAs), slice-padded counter
        if (tid == 0) {
            __threadfence();                       // publish our h slice gpu-wide
            atomicAdd(&g_bar[bg][0], 1u);
            unsigned tgt = 8u * (unsigned)(t + 1);
            while (*(volatile unsigned*)&g_bar[bg][0] < tgt) { }
            __threadfence();                       // acquire peers' h slices
        }

        // ---- history write: off the critical inter-CTA chain
        if (tid < 256)
            g_hs[((size_t)bglob * S_ + t) * H_ + ng * 64 + rj] = hn;

        __syncthreads();                           // release whole CTA
    }
}

// ---------------- launch ------------------------------------------------------
extern "C" void kernel_launch(void* const* d_in, const int* in_sizes, int n_in,
                              void* d_out, int out_size) {
    const float* inputs  = (const float*)d_in[0];
    const float* h0      = (const float*)d_in[1];
    const float* W_in_w  = (const float*)d_in[2];
    const float* W_in_b  = (const float*)d_in[3];
    const float* W_rec_w = (const float*)d_in[4];
    const float* W_out_w = (const float*)d_in[5];
    const float* W_out_b = (const float*)d_in[6];

    float* out    = (float*)d_out;                      // (B,S,O)
    float* hfinal = out + (size_t)B_ * S_ * O_;         // (B,H)

    // 1) xin = inputs @ W_in^T + b   -> g_xin          (launch #0)
    {
        dim3 grid(B_ * S_ / 128, H_ / 128);
        gemm_kernel<H_, I_, false, true><<<grid, 256>>>(inputs, W_in_w, W_in_b, nullptr);
    }
    // 2) init h double-buffer + barriers               (launch #1)
    init_kernel<<<(B_ * H_ + 255) / 256, 256>>>(h0);

    // 3) alignment dummy so ncu captures the scan      (launch #2)
    dummy_kernel<<<1, 32>>>();

    // 4) sequential scan                               (launch #3 <- ncu capture)
    scan_kernel<<<128, 512>>>(h0, W_rec_w, hfinal);

    // 5) outputs = hs @ W_out^T + b  -> d_out          (launch #4)
    {
        dim3 grid(B_ * S_ / 128, O_ / 128);
        gemm_kernel<O_, H_, true, false><<<grid, 256>>>(nullptr, W_out_w, W_out_b, out);
    }
}

// round 16
// speedup vs baseline: 1.4404x; 1.0102x over previous
#include <cuda_runtime.h>

#define B_ 64
#define S_ 2048
#define I_ 128
#define H_ 512
#define O_ 128

// ---------------- scratch (device globals: no allocations allowed) ----------
__device__ float g_xin[(size_t)B_ * S_ * H_];   // input projection (B,S,H)
__device__ float g_hs [(size_t)B_ * S_ * H_];   // hidden states   (B,S,H)
__device__ float g_h[2][B_ * H_];               // double-buffered h
__device__ unsigned g_bar[16][32];              // 128B-padded per-group barrier

// ---------------- helpers ----------------------------------------------------
__device__ __forceinline__ unsigned long long ffma2(unsigned long long a,
                                                    unsigned long long b,
                                                    unsigned long long c) {
    unsigned long long d;
    asm("fma.rn.f32x2 %0, %1, %2, %3;" : "=l"(d) : "l"(a), "l"(b), "l"(c));
    return d;
}
__device__ __forceinline__ unsigned long long pack2(float x, float y) {
    unsigned long long p;
    asm("mov.b64 %0, {%1, %2};" : "=l"(p) : "f"(x), "f"(y));
    return p;
}
__device__ __forceinline__ float2 unpack2(unsigned long long p) {
    float2 r;
    asm("mov.b64 {%0, %1}, %2;" : "=f"(r.x), "=f"(r.y) : "l"(p));
    return r;
}
__device__ __forceinline__ float tanh_approx(float x) {
    float r;
    asm("tanh.approx.f32 %0, %1;" : "=f"(r) : "f"(x));
    return r;
}
// row-dependent column swizzle (multiple of 4 -> float4-safe, bijective/row)
__device__ __forceinline__ int swz(int row) { return ((row >> 2) & 7) * 4; }

// ---------------- init: copy h0, reset barriers ------------------------------
__global__ void init_kernel(const float* __restrict__ h0) {
    int i = blockIdx.x * blockDim.x + threadIdx.x;
    if (i < B_ * H_) g_h[0][i] = h0[i];
    if (i < 16 * 32) ((unsigned*)g_bar)[i] = 0;
}

// ---------------- dummy: shifts ncu capture alignment so scan = launch #3 ----
__global__ void dummy_kernel() {}

// ---------------- tiled fp32 GEMM:  C[M,N] = A[M,K] @ B[N,K]^T + bias --------
// 128x128 block tile, 256 threads, 8x8 per-thread tile, f32x2 FMA.
// Staging stores column-swizzled by swz(row): store bank = (20j+4i+m)%32 with
// 20j%32 all-distinct -> conflict-free transpose staging (was 4-way).
// Reads XOR the same swz(kc) (uniform per instruction): A stays broadcast,
// B stays the conflict-free mb=tx pattern (R15-proven).
template <int N, int K, bool SRC_HS, bool DST_XIN>
__global__ __launch_bounds__(256) void gemm_kernel(const float* __restrict__ Ap,
                                                   const float* __restrict__ Bm,
                                                   const float* __restrict__ bias,
                                                   float* __restrict__ Cp) {
    __shared__ __align__(16) float Ast[32][132];
    __shared__ __align__(16) float Bst[32][132];
    const float* A = SRC_HS ? g_hs : Ap;
    float* C = DST_XIN ? g_xin : Cp;

    const int tid = threadIdx.x;
    const int bm = blockIdx.x, bn = blockIdx.y;
    const float* Ab = A + (size_t)bm * 128 * K;
    const float* Bb = Bm + (size_t)bn * 128 * K;

    const int tx = tid & 15, ty = tid >> 4;
    unsigned long long acc2[4][8];
#pragma unroll
    for (int i = 0; i < 4; i++)
#pragma unroll
        for (int j = 0; j < 8; j++) acc2[i][j] = 0ull;

    for (int k0 = 0; k0 < K; k0 += 32) {
#pragma unroll
        for (int u = 0; u < 4; u++) {
            int idx4 = tid + u * 256;
            int m = idx4 >> 3;
            int kq = (idx4 & 7) * 4;
            float4 va = *(const float4*)&Ab[(size_t)m * K + k0 + kq];
            Ast[kq + 0][m ^ swz(kq + 0)] = va.x;
            Ast[kq + 1][m ^ swz(kq + 1)] = va.y;
            Ast[kq + 2][m ^ swz(kq + 2)] = va.z;
            Ast[kq + 3][m ^ swz(kq + 3)] = va.w;
            float4 vb = *(const float4*)&Bb[(size_t)m * K + k0 + kq];
            Bst[kq + 0][m ^ swz(kq + 0)] = vb.x;
            Bst[kq + 1][m ^ swz(kq + 1)] = vb.y;
            Bst[kq + 2][m ^ swz(kq + 2)] = vb.z;
            Bst[kq + 3][m ^ swz(kq + 3)] = vb.w;
        }
        __syncthreads();
#pragma unroll
        for (int kc = 0; kc < 32; kc++) {
            const int s = swz(kc);
            float4 a0 = *(const float4*)&Ast[kc][(ty * 8) ^ s];
            float4 a1 = *(const float4*)&Ast[kc][(ty * 8 + 4) ^ s];
            float4 b0 = *(const float4*)&Bst[kc][(tx * 4) ^ s];
            float4 b1 = *(const float4*)&Bst[kc][(64 + tx * 4) ^ s];
            unsigned long long A2[4] = {pack2(a0.x, a0.y), pack2(a0.z, a0.w),
                                        pack2(a1.x, a1.y), pack2(a1.z, a1.w)};
            float bb[8] = {b0.x, b0.y, b0.z, b0.w, b1.x, b1.y, b1.z, b1.w};
#pragma unroll
            for (int j = 0; j < 8; j++) {
                unsigned long long B2 = pack2(bb[j], bb[j]);
#pragma unroll
                for (int i = 0; i < 4; i++) acc2[i][j] = ffma2(A2[i], B2, acc2[i][j]);
            }
        }
        __syncthreads();
    }
#pragma unroll
    for (int i = 0; i < 4; i++) {
        size_t m0 = (size_t)bm * 128 + ty * 8 + 2 * i;
#pragma unroll
        for (int j = 0; j < 8; j++) {
            int n = bn * 128 + (j < 4 ? tx * 4 + j : 64 + tx * 4 + (j - 4));
            float2 v = unpack2(acc2[i][j]);
            C[m0 * N + n]       = v.x + bias[n];
            C[(m0 + 1) * N + n] = v.y + bias[n];
        }
    }
}

// ---------------- recurrent scan (R13 frozen — best measured) ----------------
__global__ __launch_bounds__(512, 1) void scan_kernel(const float* __restrict__ h0,
                                                      const float* __restrict__ Wrec,
                                                      float* __restrict__ hfinal) {
    __shared__ __align__(16) float h_s[4 * H_];   // [b][k]
    __shared__ float red[8][4][64];               // [kg][b][j]

    const int tid = threadIdx.x;
    const int bg = blockIdx.x >> 3;   // 0..15
    const int ng = blockIdx.x & 7;    // 0..7
    const int w = tid >> 5, lane = tid & 31;
    const int kg = w >> 1;                         // 0..7 -> 64-wide K slice
    const int jl = ((w & 1) << 5) | lane;          // 0..63 local output col
    const int jg = ng * 64 + jl;                   // global output col
    const int k0 = kg * 64;

    // ---- load W_rec[jg][k0..k0+63] into registers as 32 f32x2 pairs
    unsigned long long Wr[32];
    {
        const float4* wp = (const float4*)&Wrec[(size_t)jg * H_ + k0];
#pragma unroll
        for (int i = 0; i < 16; i++) {
            float4 v = wp[i];
            Wr[2 * i]     = pack2(v.x, v.y);
            Wr[2 * i + 1] = pack2(v.z, v.w);
        }
    }

    // ---- reducer identity (first 256 threads): (rb, rj)
    const int rb = tid >> 6;          // 0..3 for tid<256
    const int rj = tid & 63;
    float xr = 0.f;
    size_t xin_base = 0;
    if (tid < 256) {
        xin_base = ((size_t)(bg * 4 + rb) * S_) * H_ + (size_t)ng * 64 + rj;
        xr = g_xin[xin_base];   // xin for t=0 (gemm ran before us, stream order)
    }

    const float* hsrc0 = h0 + (size_t)bg * 4 * H_;

    for (int t = 0; t < S_; t++) {
        // ---- load h for our 4 batches into smem (2048 floats, 1 float4/thread)
        const float* hs_src = (t == 0) ? hsrc0 : &g_h[t & 1][(size_t)bg * 4 * H_];
        ((float4*)h_s)[tid] = ((const float4*)hs_src)[tid];
        __syncthreads();

        // ---- partial GEMM: acc[b] = sum over our 64-wide K slice (f32x2)
        unsigned long long acc0 = 0, acc1 = 0, acc2 = 0, acc3 = 0;
        {
            const ulonglong2* hp0 = (const ulonglong2*)&h_s[0 * H_ + k0];
            const ulonglong2* hp1 = (const ulonglong2*)&h_s[1 * H_ + k0];
            const ulonglong2* hp2 = (const ulonglong2*)&h_s[2 * H_ + k0];
            const ulonglong2* hp3 = (const ulonglong2*)&h_s[3 * H_ + k0];
#pragma unroll
            for (int i = 0; i < 16; i++) {
                ulonglong2 u0 = hp0[i];
                acc0 = ffma2(Wr[2 * i], u0.x, acc0);
                acc0 = ffma2(Wr[2 * i + 1], u0.y, acc0);
                ulonglong2 u1 = hp1[i];
                acc1 = ffma2(Wr[2 * i], u1.x, acc1);
                acc1 = ffma2(Wr[2 * i + 1], u1.y, acc1);
                ulonglong2 u2 = hp2[i];
                acc2 = ffma2(Wr[2 * i], u2.x, acc2);
                acc2 = ffma2(Wr[2 * i + 1], u2.y, acc2);
                ulonglong2 u3 = hp3[i];
                acc3 = ffma2(Wr[2 * i], u3.x, acc3);
                acc3 = ffma2(Wr[2 * i + 1], u3.y, acc3);
            }
        }
        float2 a0 = unpack2(acc0), a1 = unpack2(acc1);
        float2 a2 = unpack2(acc2), a3 = unpack2(acc3);
        red[kg][0][jl] = a0.x + a0.y;
        red[kg][1][jl] = a1.x + a1.y;
        red[kg][2][jl] = a2.x + a2.y;
        red[kg][3][jl] = a3.x + a3.y;
        __syncthreads();

        // ---- reduce over 8 K-slices, add xin, tanh.approx, publish h
        float hn = 0.f;
        int bglob = 0;
        if (tid < 256) {
            float s = xr;
#pragma unroll
            for (int q = 0; q < 8; q++) s += red[q][rb][rj];
            hn = tanh_approx(s);
            bglob = bg * 4 + rb;
            g_h[(t + 1) & 1][(size_t)bglob * H_ + ng * 64 + rj] = hn;
            if (t == S_ - 1) hfinal[(size_t)bglob * H_ + ng * 64 + rj] = hn;
            if (t + 1 < S_) xr = g_xin[xin_base + (size_t)(t + 1) * H_]; // prefetch
        }
        __syncthreads();   // all h writes issued before the elected fence

        // ---- per-batch-group barrier (8 CTAs), slice-padded counter
        if (tid == 0) {
            __threadfence();                       // publish our h slice gpu-wide
            atomicAdd(&g_bar[bg][0], 1u);
            unsigned tgt = 8u * (unsigned)(t + 1);
            while (*(volatile unsigned*)&g_bar[bg][0] < tgt) { }
            __threadfence();                       // acquire peers' h slices
        }

        // ---- history write: off the critical inter-CTA chain
        if (tid < 256)
            g_hs[((size_t)bglob * S_ + t) * H_ + ng * 64 + rj] = hn;

        __syncthreads();                           // release whole CTA
    }
}

// ---------------- launch ------------------------------------------------------
extern "C" void kernel_launch(void* const* d_in, const int* in_sizes, int n_in,
                              void* d_out, int out_size) {
    const float* inputs  = (const float*)d_in[0];
    const float* h0      = (const float*)d_in[1];
    const float* W_in_w  = (const float*)d_in[2];
    const float* W_in_b  = (const float*)d_in[3];
    const float* W_rec_w = (const float*)d_in[4];
    const float* W_out_w = (const float*)d_in[5];
    const float* W_out_b = (const float*)d_in[6];

    float* out    = (float*)d_out;                      // (B,S,O)
    float* hfinal = out + (size_t)B_ * S_ * O_;         // (B,H)

    // 1) xin = inputs @ W_in^T + b   -> g_xin          (launch #0)
    {
        dim3 grid(B_ * S_ / 128, H_ / 128);
        gemm_kernel<H_, I_, false, true><<<grid, 256>>>(inputs, W_in_w, W_in_b, nullptr);
    }
    // 2) init h double-buffer + barriers               (launch #1)
    init_kernel<<<(B_ * H_ + 255) / 256, 256>>>(h0);

    // 3) alignment dummy so ncu captures the scan      (launch #2)
    dummy_kernel<<<1, 32>>>();

    // 4) sequential scan                               (launch #3 <- ncu capture)
    scan_kernel<<<128, 512>>>(h0, W_rec_w, hfinal);

    // 5) outputs = hs @ W_out^T + b  -> d_out          (launch #4)
    {
        dim3 grid(B_ * S_ / 128, O_ / 128);
        gemm_kernel<O_, H_, true, false><<<grid, 256>>>(nullptr, W_out_w, W_out_b, out);
    }
}